// round 9
// baseline (speedup 1.0000x reference)
#include <cuda_runtime.h>
#include <cuda_bf16.h>
#include <math.h>
#include <stdint.h>

#define DIMC 256
#define HEADS 8
#define HD 32
#define TTOK 131072          // 32*4096 tokens
#define HIDD 1024

// ---------------- scratch (static __device__, no allocs) ----------------
__device__ __nv_bfloat16 g_xw  [(size_t)TTOK * DIMC];
__device__ __nv_bfloat16 g_qkv [(size_t)TTOK * 3 * DIMC];
__device__ __nv_bfloat16 g_attn[(size_t)TTOK * DIMC];
__device__ float         g_x1  [(size_t)TTOK * DIMC];      // window order
__device__ __nv_bfloat16 g_xn2 [(size_t)TTOK * DIMC];      // window order
__device__ __nv_bfloat16 g_h   [(size_t)TTOK * HIDD];      // window order
__device__ __nv_bfloat16 g_wall[(3 * DIMC + DIMC + HIDD + DIMC) * DIMC + DIMC * HIDD];
__device__ float         g_bias[HEADS * 64 * 64];

#define WOFF_QKV  0
#define WOFF_PROJ (3 * DIMC * DIMC)
#define WOFF_FC1  (WOFF_PROJ + DIMC * DIMC)
#define WOFF_FC2  (WOFF_FC1 + HIDD * DIMC)
#define WTOT      (WOFF_FC2 + DIMC * HIDD)

// ---------------- helpers ----------------
__device__ __forceinline__ uint32_t smem_u32(const void* p) {
    return (uint32_t)__cvta_generic_to_shared(p);
}
__device__ __forceinline__ void cp_async16(uint32_t saddr, const void* gptr) {
    asm volatile("cp.async.cg.shared.global [%0], [%1], 16;\n" :: "r"(saddr), "l"(gptr));
}
__device__ __forceinline__ void cp_commit() { asm volatile("cp.async.commit_group;\n"); }
__device__ __forceinline__ void ldmatrix_x4(uint32_t& r0, uint32_t& r1, uint32_t& r2, uint32_t& r3, uint32_t addr) {
    asm volatile("ldmatrix.sync.aligned.m8n8.x4.shared.b16 {%0,%1,%2,%3}, [%4];\n"
                 : "=r"(r0), "=r"(r1), "=r"(r2), "=r"(r3) : "r"(addr));
}
__device__ __forceinline__ void ldmatrix_x2_trans(uint32_t& r0, uint32_t& r1, uint32_t addr) {
    asm volatile("ldmatrix.sync.aligned.m8n8.x2.trans.shared.b16 {%0,%1}, [%2];\n"
                 : "=r"(r0), "=r"(r1) : "r"(addr));
}
__device__ __forceinline__ void mma_bf16(float c[4], const uint32_t a[4], const uint32_t b[2]) {
    asm volatile("mma.sync.aligned.m16n8k16.row.col.f32.bf16.bf16.f32 "
                 "{%0,%1,%2,%3}, {%4,%5,%6,%7}, {%8,%9}, {%0,%1,%2,%3};\n"
                 : "+f"(c[0]), "+f"(c[1]), "+f"(c[2]), "+f"(c[3])
                 : "r"(a[0]), "r"(a[1]), "r"(a[2]), "r"(a[3]), "r"(b[0]), "r"(b[1]));
}
__device__ __forceinline__ float gelu_f(float v) {
    return 0.5f * v * (1.0f + erff(v * 0.7071067811865476f));
}
__device__ __forceinline__ int orig_to_win(int t) {
    int b = t >> 12, rem = t & 4095;
    int r = rem >> 6, c = rem & 63;
    int wi = (b << 6) + ((r >> 3) << 3) + (c >> 3);
    return (wi << 6) + ((r & 7) << 3) + (c & 7);
}
__device__ __forceinline__ int win_to_orig(int tw) {
    int wi = tw >> 6, k = tw & 63;
    int b = wi >> 6, w64 = wi & 63;
    int r = ((w64 >> 3) << 3) + (k >> 3);
    int c = ((w64 & 7) << 3) + (k & 7);
    return (b << 12) + (r << 6) + c;
}

// ---------------- fused weight convert ----------------
__global__ void cvt_all_kernel(const float* __restrict__ wqkv, const float* __restrict__ wproj,
                               const float* __restrict__ wfc1, const float* __restrict__ wfc2,
                               __nv_bfloat16* __restrict__ out) {
    int i = blockIdx.x * blockDim.x + threadIdx.x;
    const float* src;
    int li = i * 4;
    if (li < WOFF_PROJ)        { src = wqkv  + li - WOFF_QKV; }
    else if (li < WOFF_FC1)    { src = wproj + li - WOFF_PROJ; }
    else if (li < WOFF_FC2)    { src = wfc1  + li - WOFF_FC1; }
    else                       { src = wfc2  + li - WOFF_FC2; }
    float4 v = *(const float4*)src;
    ((__nv_bfloat162*)out)[2 * i]     = __floats2bfloat162_rn(v.x, v.y);
    ((__nv_bfloat162*)out)[2 * i + 1] = __floats2bfloat162_rn(v.z, v.w);
}

// ---------------- bias table precompute: g_bias[h][n][m] ----------------
__global__ void bias_kernel(const float* __restrict__ btab, float* __restrict__ bout) {
    int t = blockIdx.x * blockDim.x + threadIdx.x;
    int m = t & 63, n = (t >> 6) & 63, h = t >> 12;
    int rel = ((n >> 3) - (m >> 3) + 7) * 15 + ((n & 7) - (m & 7) + 7);
    bout[t] = btab[rel * 8 + h];
}

// ---------------- LayerNorm (warp per token), optional window-permute ----------------
template<int PERM>
__global__ __launch_bounds__(256) void ln_kernel(const float* __restrict__ x,
                                                 const float* __restrict__ g,
                                                 const float* __restrict__ b,
                                                 __nv_bfloat16* __restrict__ out) {
    int warp = (blockIdx.x * 256 + threadIdx.x) >> 5;
    int lane = threadIdx.x & 31;
    const float* row = x + (size_t)warp * DIMC + lane * 8;
    float4 v0 = *(const float4*)row;
    float4 v1 = *(const float4*)(row + 4);
    float s = (v0.x + v0.y) + (v0.z + v0.w) + ((v1.x + v1.y) + (v1.z + v1.w));
#pragma unroll
    for (int o = 16; o; o >>= 1) s += __shfl_xor_sync(0xffffffffu, s, o);
    float mu = s * (1.0f / 256.0f);
    float d[8] = { v0.x - mu, v0.y - mu, v0.z - mu, v0.w - mu,
                   v1.x - mu, v1.y - mu, v1.z - mu, v1.w - mu };
    float ss = 0.f;
#pragma unroll
    for (int i = 0; i < 8; i++) ss += d[i] * d[i];
#pragma unroll
    for (int o = 16; o; o >>= 1) ss += __shfl_xor_sync(0xffffffffu, ss, o);
    float rstd = rsqrtf(ss * (1.0f / 256.0f) + 1e-5f);
    float4 gg0 = *(const float4*)(g + lane * 8);
    float4 gg1 = *(const float4*)(g + lane * 8 + 4);
    float4 bb0 = *(const float4*)(b + lane * 8);
    float4 bb1 = *(const float4*)(b + lane * 8 + 4);
    float y[8];
    y[0] = d[0] * rstd * gg0.x + bb0.x;  y[1] = d[1] * rstd * gg0.y + bb0.y;
    y[2] = d[2] * rstd * gg0.z + bb0.z;  y[3] = d[3] * rstd * gg0.w + bb0.w;
    y[4] = d[4] * rstd * gg1.x + bb1.x;  y[5] = d[5] * rstd * gg1.y + bb1.y;
    y[6] = d[6] * rstd * gg1.z + bb1.z;  y[7] = d[7] * rstd * gg1.w + bb1.w;
    int orow = PERM ? orig_to_win(warp) : warp;
    __nv_bfloat16* op = out + (size_t)orow * DIMC + lane * 8;
    __nv_bfloat162 p0 = __floats2bfloat162_rn(y[0], y[1]);
    __nv_bfloat162 p1 = __floats2bfloat162_rn(y[2], y[3]);
    __nv_bfloat162 p2 = __floats2bfloat162_rn(y[4], y[5]);
    __nv_bfloat162 p3 = __floats2bfloat162_rn(y[6], y[7]);
    uint4 pk;
    pk.x = *(uint32_t*)&p0; pk.y = *(uint32_t*)&p1; pk.z = *(uint32_t*)&p2; pk.w = *(uint32_t*)&p3;
    *(uint4*)op = pk;
}

// ---------------- bf16 TN GEMM: C[M,N] = A[M,K] @ B[N,K]^T ----------------
// Tile 128x128, 4 warps (2M x 2N), warp tile 64x64 -> 8 LDSM : 32 HMMA per k16.
// 3-stage cp.async ring (96KB), 2 CTAs/SM (8 warps).
#define BM 128
#define BN 128
#define BKK 64
#define STG 32768            // A 16KB + B 16KB per stage
#define GSMEM (3 * STG)      // 98304

template<int N, int K, int EPI>
__global__ __launch_bounds__(128, 2) void gemm_kernel(const __nv_bfloat16* __restrict__ A,
                                                      const __nv_bfloat16* __restrict__ Bw,
                                                      const float* __restrict__ bias,
                                                      const float* __restrict__ res,
                                                      float* __restrict__ outf,
                                                      __nv_bfloat16* __restrict__ outb) {
    extern __shared__ uint8_t dynsm[];
    const int tid = threadIdx.x;
    const int lane = tid & 31;
    const int wid = tid >> 5;
    const int wm = wid & 1;      // 2 warps along M (64 rows each)
    const int wn = wid >> 1;     // 2 warps along N (64 cols each)
    const size_t m0 = (size_t)blockIdx.x * BM;
    const int n0 = blockIdx.y * BN;
    const uint32_t sbase = smem_u32(dynsm);

    float acc[4][8][4];
#pragma unroll
    for (int a = 0; a < 4; a++)
#pragma unroll
        for (int bq = 0; bq < 8; bq++)
#pragma unroll
            for (int c = 0; c < 4; c++) acc[a][bq][c] = 0.f;

    auto load_stage = [&](int s, int kt) {
        uint32_t abase = sbase + (uint32_t)s * STG;
        uint32_t bbase = abase + 16384;
        int k0 = kt * BKK;
#pragma unroll
        for (int i = 0; i < 8; i++) {
            int ch = tid + i * 128;
            int row = ch >> 3, kc = ch & 7;
            const __nv_bfloat16* ga = A + (m0 + row) * K + k0 + kc * 8;
            cp_async16(abase + ((((uint32_t)row << 3) | (uint32_t)(kc ^ (row & 7))) << 4), ga);
        }
#pragma unroll
        for (int i = 0; i < 8; i++) {
            int ch = tid + i * 128;
            int row = ch >> 3, kc = ch & 7;
            const __nv_bfloat16* gb = Bw + (size_t)(n0 + row) * K + k0 + kc * 8;
            cp_async16(bbase + ((((uint32_t)row << 3) | (uint32_t)(kc ^ (row & 7))) << 4), gb);
        }
        cp_commit();
    };

    constexpr int KT = K / BKK;
    load_stage(0, 0);
    load_stage(1, 1);
    const int ti = lane >> 3, rr = lane & 7;
    const int arow0 = wm * 64 + ((ti & 1) ? 8 : 0) + rr;   // + mt*16
    const int akc0  = ti >> 1;                             // + ks*2
    const int brow0 = wn * 64 + ((ti >> 1) ? 8 : 0) + rr;  // + ng*16
    const int bkc0  = ti & 1;                              // + ks*2

#pragma unroll 1
    for (int kt = 0; kt < KT; kt++) {
        asm volatile("cp.async.wait_group 1;\n" ::: "memory");
        __syncthreads();
        if (kt + 2 < KT) load_stage((kt + 2) % 3, kt + 2);
        uint32_t abase = sbase + (uint32_t)(kt % 3) * STG;
        uint32_t bbase = abase + 16384;
#pragma unroll
        for (int ks = 0; ks < 4; ks++) {
            int kca = ks * 2 + akc0;
            int kcb = ks * 2 + bkc0;
            uint32_t afr[4][4];
#pragma unroll
            for (int mt = 0; mt < 4; mt++) {
                int row = arow0 + mt * 16;
                uint32_t addr = abase + ((((uint32_t)row << 3) | (uint32_t)(kca ^ (row & 7))) << 4);
                ldmatrix_x4(afr[mt][0], afr[mt][1], afr[mt][2], afr[mt][3], addr);
            }
            uint32_t bfr[8][2];
#pragma unroll
            for (int ng = 0; ng < 4; ng++) {
                int row = brow0 + ng * 16;
                uint32_t addr = bbase + ((((uint32_t)row << 3) | (uint32_t)(kcb ^ (row & 7))) << 4);
                uint32_t r0, r1, r2, r3;
                ldmatrix_x4(r0, r1, r2, r3, addr);
                bfr[2 * ng][0] = r0;     bfr[2 * ng][1] = r1;
                bfr[2 * ng + 1][0] = r2; bfr[2 * ng + 1][1] = r3;
            }
#pragma unroll
            for (int mt = 0; mt < 4; mt++)
#pragma unroll
                for (int nt = 0; nt < 8; nt++)
                    mma_bf16(acc[mt][nt], afr[mt], bfr[nt]);
        }
    }

    // -------- epilogue --------
    int lrow = lane >> 2, lc2 = (lane & 3) * 2;
#pragma unroll
    for (int mt = 0; mt < 4; mt++) {
#pragma unroll
        for (int hh = 0; hh < 2; hh++) {
            int r = (int)m0 + wm * 64 + mt * 16 + lrow + hh * 8;
            if constexpr (EPI == 0 || EPI == 2) {
                __nv_bfloat16* op = outb + (size_t)r * N;
#pragma unroll
                for (int nt = 0; nt < 8; nt++) {
                    int c = n0 + wn * 64 + nt * 8 + lc2;
                    float2 bb = *(const float2*)(bias + c);
                    float v0 = acc[mt][nt][2 * hh + 0] + bb.x;
                    float v1 = acc[mt][nt][2 * hh + 1] + bb.y;
                    if constexpr (EPI == 2) { v0 = gelu_f(v0); v1 = gelu_f(v1); }
                    *(__nv_bfloat162*)(op + c) = __floats2bfloat162_rn(v0, v1);
                }
            } else if constexpr (EPI == 1) {
                int torig = win_to_orig(r);
                const float* xr = res + (size_t)torig * 256;
                float* op = outf + (size_t)r * 256;
#pragma unroll
                for (int nt = 0; nt < 8; nt++) {
                    int c = n0 + wn * 64 + nt * 8 + lc2;
                    float2 bb = *(const float2*)(bias + c);
                    float2 xres = *(const float2*)(xr + c);
                    *(float2*)(op + c) = make_float2(xres.x + acc[mt][nt][2 * hh + 0] + bb.x,
                                                     xres.y + acc[mt][nt][2 * hh + 1] + bb.y);
                }
            } else {
                int torig = win_to_orig(r);
                const float* x1r = res + (size_t)r * 256;
                float* op = outf + (size_t)torig * 256;
#pragma unroll
                for (int nt = 0; nt < 8; nt++) {
                    int c = n0 + wn * 64 + nt * 8 + lc2;
                    float2 bb = *(const float2*)(bias + c);
                    float v0 = acc[mt][nt][2 * hh + 0] + bb.x;
                    float v1 = acc[mt][nt][2 * hh + 1] + bb.y;
                    float2 rr2 = *(const float2*)(x1r + c);
                    *(float2*)(op + c) = make_float2(rr2.x + v0, rr2.y + v1);
                }
            }
        }
    }
}

// ---------------- windowed attention via mma.sync: 1 CTA/window, warp=head ----------------
#define ATT_PITCH 1552
#define ATT_SMEM (64 * ATT_PITCH)

__global__ __launch_bounds__(256, 2) void attn_kernel(const __nv_bfloat16* __restrict__ qkv,
                                                      const float* __restrict__ bias_pre,
                                                      __nv_bfloat16* __restrict__ out) {
    extern __shared__ __align__(128) uint8_t dynsm[];
    const int w = blockIdx.x;
    const int tid = threadIdx.x;
    const int h = tid >> 5, lane = tid & 31;
    const uint32_t sb = smem_u32(dynsm);
    const __nv_bfloat16* gw = qkv + (size_t)w * 49152;

#pragma unroll
    for (int i = 0; i < 24; i++) {
        int ch = tid + i * 256;
        int r = ch / 96, c = ch % 96;
        cp_async16(sb + (uint32_t)(r * ATT_PITCH + c * 16), gw + r * 768 + c * 8);
    }
    cp_commit();
    asm volatile("cp.async.wait_group 0;\n" ::: "memory");
    __syncthreads();

    const uint32_t qbase = sb + (uint32_t)(h * 32) * 2;
    const uint32_t kbase = sb + (uint32_t)(256 + h * 32) * 2;
    const uint32_t vbase = sb + (uint32_t)(512 + h * 32) * 2;
    const float* bp = bias_pre + h * 4096;
    const float scale = 0.17677669529663688f;
    const int ti = lane >> 3, rr = lane & 7;
    const int lq = lane >> 2, lc = (lane & 3) * 2;

#pragma unroll 1
    for (int i = 0; i < 4; i++) {
        uint32_t qf[2][4];
#pragma unroll
        for (int ks = 0; ks < 2; ks++) {
            int row = i * 16 + ((ti & 1) ? 8 : 0) + rr;
            uint32_t addr = qbase + (uint32_t)(row * ATT_PITCH) + (uint32_t)((ks * 2 + (ti >> 1)) * 16);
            ldmatrix_x4(qf[ks][0], qf[ks][1], qf[ks][2], qf[ks][3], addr);
        }
        float sacc[8][4];
#pragma unroll
        for (int j = 0; j < 8; j++)
#pragma unroll
            for (int c = 0; c < 4; c++) sacc[j][c] = 0.f;
#pragma unroll
        for (int ks = 0; ks < 2; ks++) {
#pragma unroll
            for (int ng = 0; ng < 4; ng++) {
                int row = ng * 16 + ((ti >> 1) ? 8 : 0) + rr;
                uint32_t addr = kbase + (uint32_t)(row * ATT_PITCH) + (uint32_t)((ks * 2 + (ti & 1)) * 16);
                uint32_t b0, b1, b2, b3;
                ldmatrix_x4(b0, b1, b2, b3, addr);
                uint32_t bf0[2] = { b0, b1 }, bf1[2] = { b2, b3 };
                mma_bf16(sacc[2 * ng],     qf[ks], bf0);
                mma_bf16(sacc[2 * ng + 1], qf[ks], bf1);
            }
        }
        int r0 = i * 16 + lq, r1 = r0 + 8;
        float p[8][4];
        float mx0 = -1e30f, mx1 = -1e30f;
#pragma unroll
        for (int j = 0; j < 8; j++) {
            float2 b0 = *(const float2*)(bp + r0 * 64 + j * 8 + lc);
            float2 b1 = *(const float2*)(bp + r1 * 64 + j * 8 + lc);
            p[j][0] = fmaf(sacc[j][0], scale, b0.x);
            p[j][1] = fmaf(sacc[j][1], scale, b0.y);
            p[j][2] = fmaf(sacc[j][2], scale, b1.x);
            p[j][3] = fmaf(sacc[j][3], scale, b1.y);
            mx0 = fmaxf(mx0, fmaxf(p[j][0], p[j][1]));
            mx1 = fmaxf(mx1, fmaxf(p[j][2], p[j][3]));
        }
        mx0 = fmaxf(mx0, __shfl_xor_sync(0xffffffffu, mx0, 1));
        mx0 = fmaxf(mx0, __shfl_xor_sync(0xffffffffu, mx0, 2));
        mx1 = fmaxf(mx1, __shfl_xor_sync(0xffffffffu, mx1, 1));
        mx1 = fmaxf(mx1, __shfl_xor_sync(0xffffffffu, mx1, 2));
        float sm0 = 0.f, sm1 = 0.f;
#pragma unroll
        for (int j = 0; j < 8; j++) {
            p[j][0] = __expf(p[j][0] - mx0);
            p[j][1] = __expf(p[j][1] - mx0);
            p[j][2] = __expf(p[j][2] - mx1);
            p[j][3] = __expf(p[j][3] - mx1);
            sm0 += p[j][0] + p[j][1];
            sm1 += p[j][2] + p[j][3];
        }
        sm0 += __shfl_xor_sync(0xffffffffu, sm0, 1);
        sm0 += __shfl_xor_sync(0xffffffffu, sm0, 2);
        sm1 += __shfl_xor_sync(0xffffffffu, sm1, 1);
        sm1 += __shfl_xor_sync(0xffffffffu, sm1, 2);
        float inv0 = 1.0f / sm0, inv1 = 1.0f / sm1;

        uint32_t ap[4][4];
#pragma unroll
        for (int ks = 0; ks < 4; ks++) {
            __nv_bfloat162 t0 = __floats2bfloat162_rn(p[2 * ks][0],     p[2 * ks][1]);
            __nv_bfloat162 t1 = __floats2bfloat162_rn(p[2 * ks][2],     p[2 * ks][3]);
            __nv_bfloat162 t2 = __floats2bfloat162_rn(p[2 * ks + 1][0], p[2 * ks + 1][1]);
            __nv_bfloat162 t3 = __floats2bfloat162_rn(p[2 * ks + 1][2], p[2 * ks + 1][3]);
            ap[ks][0] = *(uint32_t*)&t0; ap[ks][1] = *(uint32_t*)&t1;
            ap[ks][2] = *(uint32_t*)&t2; ap[ks][3] = *(uint32_t*)&t3;
        }
        float o[4][4];
#pragma unroll
        for (int jj = 0; jj < 4; jj++)
#pragma unroll
            for (int c = 0; c < 4; c++) o[jj][c] = 0.f;
#pragma unroll
        for (int ks = 0; ks < 4; ks++) {
#pragma unroll
            for (int jj = 0; jj < 4; jj++) {
                uint32_t bv[2];
                uint32_t addr = vbase + (uint32_t)((ks * 16 + (lane & 15)) * ATT_PITCH) + (uint32_t)(jj * 16);
                ldmatrix_x2_trans(bv[0], bv[1], addr);
                mma_bf16(o[jj], ap[ks], bv);
            }
        }
        __nv_bfloat16* out0 = out + (size_t)(w * 64 + r0) * 256 + h * 32 + lc;
        __nv_bfloat16* out1 = out + (size_t)(w * 64 + r1) * 256 + h * 32 + lc;
#pragma unroll
        for (int jj = 0; jj < 4; jj++) {
            *(__nv_bfloat162*)(out0 + jj * 8) = __floats2bfloat162_rn(o[jj][0] * inv0, o[jj][1] * inv0);
            *(__nv_bfloat162*)(out1 + jj * 8) = __floats2bfloat162_rn(o[jj][2] * inv1, o[jj][3] * inv1);
        }
    }
}

// ---------------- launch ----------------
extern "C" void kernel_launch(void* const* d_in, const int* in_sizes, int n_in,
                              void* d_out, int out_size) {
    const float* x      = (const float*)d_in[0];
    const float* g1     = (const float*)d_in[2];
    const float* b1     = (const float*)d_in[3];
    const float* w_qkv  = (const float*)d_in[4];
    const float* b_qkv  = (const float*)d_in[5];
    const float* btab   = (const float*)d_in[6];
    const float* w_proj = (const float*)d_in[7];
    const float* b_proj = (const float*)d_in[8];
    const float* g2     = (const float*)d_in[9];
    const float* b2     = (const float*)d_in[10];
    const float* w_fc1  = (const float*)d_in[11];
    const float* b_fc1  = (const float*)d_in[12];
    const float* w_fc2  = (const float*)d_in[13];
    const float* b_fc2  = (const float*)d_in[14];
    float* out = (float*)d_out;

    __nv_bfloat16 *xw, *qkv, *attn, *xn2, *hbuf, *wall;
    float *x1, *bpre;
    cudaGetSymbolAddress((void**)&xw,   g_xw);
    cudaGetSymbolAddress((void**)&qkv,  g_qkv);
    cudaGetSymbolAddress((void**)&attn, g_attn);
    cudaGetSymbolAddress((void**)&x1,   g_x1);
    cudaGetSymbolAddress((void**)&xn2,  g_xn2);
    cudaGetSymbolAddress((void**)&hbuf, g_h);
    cudaGetSymbolAddress((void**)&wall, g_wall);
    cudaGetSymbolAddress((void**)&bpre, g_bias);

    __nv_bfloat16* wq = wall + WOFF_QKV;
    __nv_bfloat16* wp = wall + WOFF_PROJ;
    __nv_bfloat16* w1 = wall + WOFF_FC1;
    __nv_bfloat16* w2 = wall + WOFF_FC2;

    cudaFuncSetAttribute(gemm_kernel<768, 256, 0>,  cudaFuncAttributeMaxDynamicSharedMemorySize, GSMEM);
    cudaFuncSetAttribute(gemm_kernel<256, 256, 1>,  cudaFuncAttributeMaxDynamicSharedMemorySize, GSMEM);
    cudaFuncSetAttribute(gemm_kernel<1024, 256, 2>, cudaFuncAttributeMaxDynamicSharedMemorySize, GSMEM);
    cudaFuncSetAttribute(gemm_kernel<256, 1024, 3>, cudaFuncAttributeMaxDynamicSharedMemorySize, GSMEM);
    cudaFuncSetAttribute(attn_kernel, cudaFuncAttributeMaxDynamicSharedMemorySize, ATT_SMEM);

    cvt_all_kernel<<<WTOT / 4 / 256, 256>>>(w_qkv, w_proj, w_fc1, w_fc2, wall);
    bias_kernel<<<HEADS * 64 * 64 / 256, 256>>>(btab, bpre);
    ln_kernel<1><<<TTOK / 8, 256>>>(x, g1, b1, xw);
    gemm_kernel<768, 256, 0><<<dim3(TTOK / 128, 6), 128, GSMEM>>>(
        xw, wq, b_qkv, nullptr, nullptr, qkv);
    attn_kernel<<<2048, 256, ATT_SMEM>>>(qkv, bpre, attn);
    gemm_kernel<256, 256, 1><<<dim3(TTOK / 128, 2), 128, GSMEM>>>(
        attn, wp, b_proj, x, x1, nullptr);
    ln_kernel<0><<<TTOK / 8, 256>>>(x1, g2, b2, xn2);
    gemm_kernel<1024, 256, 2><<<dim3(TTOK / 128, 8), 128, GSMEM>>>(
        xn2, w1, b_fc1, nullptr, nullptr, hbuf);
    gemm_kernel<256, 1024, 3><<<dim3(TTOK / 128, 2), 128, GSMEM>>>(
        hbuf, w2, b_fc2, x1, out, nullptr);
}

// round 10
// speedup vs baseline: 1.0063x; 1.0063x over previous
#include <cuda_runtime.h>
#include <cuda_bf16.h>
#include <math.h>
#include <stdint.h>

#define DIMC 256
#define HEADS 8
#define TTOK 131072          // 32*4096 tokens
#define HIDD 1024

// ---------------- scratch (static __device__, no allocs) ----------------
// GEMM-A activations + weights live as swizzled 16KB tile images:
//   tile index = (row>>7)*(K/64) + (k>>6); within tile:
//   byte = (row&127)*128 + ((((k&63)>>3) ^ (row&7))<<4) + (k&7)*2
__device__ __align__(128) __nv_bfloat16 g_xw  [(size_t)TTOK * DIMC];     // swizzled, K=256
__device__ __align__(128) __nv_bfloat16 g_qkv [(size_t)TTOK * 3 * DIMC]; // LINEAR (attn input)
__device__ __align__(128) __nv_bfloat16 g_attn[(size_t)TTOK * DIMC];     // swizzled, K=256
__device__ __align__(128) float         g_x1  [(size_t)TTOK * DIMC];     // linear fp32, window order
__device__ __align__(128) __nv_bfloat16 g_xn2 [(size_t)TTOK * DIMC];     // swizzled, K=256
__device__ __align__(128) __nv_bfloat16 g_h   [(size_t)TTOK * HIDD];     // swizzled, K=1024
__device__ __align__(128) __nv_bfloat16 g_wall[(3 * DIMC + DIMC + HIDD + DIMC) * DIMC + DIMC * HIDD]; // swizzled
__device__ float         g_bias[HEADS * 64 * 64];

#define WOFF_QKV  0
#define WOFF_PROJ (3 * DIMC * DIMC)
#define WOFF_FC1  (WOFF_PROJ + DIMC * DIMC)
#define WOFF_FC2  (WOFF_FC1 + HIDD * DIMC)
#define WTOT      (WOFF_FC2 + DIMC * HIDD)

// ---------------- helpers ----------------
__device__ __forceinline__ uint32_t smem_u32(const void* p) {
    return (uint32_t)__cvta_generic_to_shared(p);
}
__device__ __forceinline__ void cp_async16(uint32_t saddr, const void* gptr) {
    asm volatile("cp.async.cg.shared.global [%0], [%1], 16;\n" :: "r"(saddr), "l"(gptr));
}
__device__ __forceinline__ void cp_commit() { asm volatile("cp.async.commit_group;\n"); }
__device__ __forceinline__ void bulk_g2s(uint32_t dst, const void* src, uint32_t bytes, uint32_t mbar) {
    asm volatile("cp.async.bulk.shared::cluster.global.mbarrier::complete_tx::bytes [%0], [%1], %2, [%3];"
                 :: "r"(dst), "l"(src), "r"(bytes), "r"(mbar) : "memory");
}
__device__ __forceinline__ void mbar_init(uint32_t mbar, uint32_t cnt) {
    asm volatile("mbarrier.init.shared.b64 [%0], %1;" :: "r"(mbar), "r"(cnt) : "memory");
}
__device__ __forceinline__ void mbar_expect_tx(uint32_t mbar, uint32_t bytes) {
    asm volatile("mbarrier.arrive.expect_tx.shared.b64 _, [%0], %1;" :: "r"(mbar), "r"(bytes) : "memory");
}
__device__ __forceinline__ void mbar_wait(uint32_t mbar, uint32_t parity) {
    asm volatile("{\n\t.reg .pred P1;\n\t"
                 "WAIT_%=:\n\t"
                 "mbarrier.try_wait.parity.acquire.cta.shared::cta.b64 P1, [%0], %1, 0x989680;\n\t"
                 "@P1 bra.uni DONE_%=;\n\t"
                 "bra.uni WAIT_%=;\n\t"
                 "DONE_%=:\n\t}"
                 :: "r"(mbar), "r"(parity) : "memory");
}
__device__ __forceinline__ void ldmatrix_x4(uint32_t& r0, uint32_t& r1, uint32_t& r2, uint32_t& r3, uint32_t addr) {
    asm volatile("ldmatrix.sync.aligned.m8n8.x4.shared.b16 {%0,%1,%2,%3}, [%4];\n"
                 : "=r"(r0), "=r"(r1), "=r"(r2), "=r"(r3) : "r"(addr));
}
__device__ __forceinline__ void ldmatrix_x2_trans(uint32_t& r0, uint32_t& r1, uint32_t addr) {
    asm volatile("ldmatrix.sync.aligned.m8n8.x2.trans.shared.b16 {%0,%1}, [%2];\n"
                 : "=r"(r0), "=r"(r1) : "r"(addr));
}
__device__ __forceinline__ void mma_bf16(float c[4], const uint32_t a[4], const uint32_t b[2]) {
    asm volatile("mma.sync.aligned.m16n8k16.row.col.f32.bf16.bf16.f32 "
                 "{%0,%1,%2,%3}, {%4,%5,%6,%7}, {%8,%9}, {%0,%1,%2,%3};\n"
                 : "+f"(c[0]), "+f"(c[1]), "+f"(c[2]), "+f"(c[3])
                 : "r"(a[0]), "r"(a[1]), "r"(a[2]), "r"(a[3]), "r"(b[0]), "r"(b[1]));
}
__device__ __forceinline__ float gelu_f(float v) {
    return 0.5f * v * (1.0f + erff(v * 0.7071067811865476f));
}
__device__ __forceinline__ int orig_to_win(int t) {
    int b = t >> 12, rem = t & 4095;
    int r = rem >> 6, c = rem & 63;
    int wi = (b << 6) + ((r >> 3) << 3) + (c >> 3);
    return (wi << 6) + ((r & 7) << 3) + (c & 7);
}
__device__ __forceinline__ int win_to_orig(int tw) {
    int wi = tw >> 6, k = tw & 63;
    int b = wi >> 6, w64 = wi & 63;
    int r = ((w64 >> 3) << 3) + (k >> 3);
    int c = ((w64 & 7) << 3) + (k & 7);
    return (b << 12) + (r << 6) + c;
}
// swizzled gmem byte offset for (row, k) in a K=Kd matrix tile image
__device__ __forceinline__ size_t swz_off(int row, int k, int Kd) {
    return ((size_t)((row >> 7) * (Kd >> 6) + (k >> 6)) << 14)
         + (size_t)((row & 127) * 128 + ((((k & 63) >> 3) ^ (row & 7)) << 4) + (k & 7) * 2);
}

// ---------------- fused weight convert -> swizzled tiles ----------------
__global__ void cvt_all_kernel(const float* __restrict__ wqkv, const float* __restrict__ wproj,
                               const float* __restrict__ wfc1, const float* __restrict__ wfc2,
                               __nv_bfloat16* __restrict__ out) {
    int i = blockIdx.x * blockDim.x + threadIdx.x;
    int li = i * 8;
    const float* src; size_t basebyte; int Kd; int loc;
    if (li < WOFF_PROJ)      { src = wqkv;  loc = li;             basebyte = 0;                    Kd = 256; }
    else if (li < WOFF_FC1)  { src = wproj; loc = li - WOFF_PROJ; basebyte = (size_t)WOFF_PROJ*2;  Kd = 256; }
    else if (li < WOFF_FC2)  { src = wfc1;  loc = li - WOFF_FC1;  basebyte = (size_t)WOFF_FC1*2;   Kd = 256; }
    else                     { src = wfc2;  loc = li - WOFF_FC2;  basebyte = (size_t)WOFF_FC2*2;   Kd = 1024; }
    float4 a = *(const float4*)(src + loc);
    float4 b = *(const float4*)(src + loc + 4);
    int row = loc / Kd, k = loc % Kd;
    size_t off = basebyte + swz_off(row, k, Kd);
    __nv_bfloat162 p0 = __floats2bfloat162_rn(a.x, a.y);
    __nv_bfloat162 p1 = __floats2bfloat162_rn(a.z, a.w);
    __nv_bfloat162 p2 = __floats2bfloat162_rn(b.x, b.y);
    __nv_bfloat162 p3 = __floats2bfloat162_rn(b.z, b.w);
    uint4 pk;
    pk.x = *(uint32_t*)&p0; pk.y = *(uint32_t*)&p1; pk.z = *(uint32_t*)&p2; pk.w = *(uint32_t*)&p3;
    *(uint4*)((char*)out + off) = pk;
}

// ---------------- bias table precompute: g_bias[h][n][m] ----------------
__global__ void bias_kernel(const float* __restrict__ btab, float* __restrict__ bout) {
    int t = blockIdx.x * blockDim.x + threadIdx.x;
    int m = t & 63, n = (t >> 6) & 63, h = t >> 12;
    int rel = ((n >> 3) - (m >> 3) + 7) * 15 + ((n & 7) - (m & 7) + 7);
    bout[t] = btab[rel * 8 + h];
}

// ---------------- LayerNorm (warp per token) -> swizzled out (K=256) ----------------
template<int PERM>
__global__ __launch_bounds__(256) void ln_kernel(const float* __restrict__ x,
                                                 const float* __restrict__ g,
                                                 const float* __restrict__ b,
                                                 __nv_bfloat16* __restrict__ out) {
    int warp = (blockIdx.x * 256 + threadIdx.x) >> 5;
    int lane = threadIdx.x & 31;
    const float* row = x + (size_t)warp * DIMC + lane * 8;
    float4 v0 = *(const float4*)row;
    float4 v1 = *(const float4*)(row + 4);
    float s = (v0.x + v0.y) + (v0.z + v0.w) + ((v1.x + v1.y) + (v1.z + v1.w));
#pragma unroll
    for (int o = 16; o; o >>= 1) s += __shfl_xor_sync(0xffffffffu, s, o);
    float mu = s * (1.0f / 256.0f);
    float d[8] = { v0.x - mu, v0.y - mu, v0.z - mu, v0.w - mu,
                   v1.x - mu, v1.y - mu, v1.z - mu, v1.w - mu };
    float ss = 0.f;
#pragma unroll
    for (int i = 0; i < 8; i++) ss += d[i] * d[i];
#pragma unroll
    for (int o = 16; o; o >>= 1) ss += __shfl_xor_sync(0xffffffffu, ss, o);
    float rstd = rsqrtf(ss * (1.0f / 256.0f) + 1e-5f);
    float4 gg0 = *(const float4*)(g + lane * 8);
    float4 gg1 = *(const float4*)(g + lane * 8 + 4);
    float4 bb0 = *(const float4*)(b + lane * 8);
    float4 bb1 = *(const float4*)(b + lane * 8 + 4);
    float y[8];
    y[0] = d[0] * rstd * gg0.x + bb0.x;  y[1] = d[1] * rstd * gg0.y + bb0.y;
    y[2] = d[2] * rstd * gg0.z + bb0.z;  y[3] = d[3] * rstd * gg0.w + bb0.w;
    y[4] = d[4] * rstd * gg1.x + bb1.x;  y[5] = d[5] * rstd * gg1.y + bb1.y;
    y[6] = d[6] * rstd * gg1.z + bb1.z;  y[7] = d[7] * rstd * gg1.w + bb1.w;
    int orow = PERM ? orig_to_win(warp) : warp;
    __nv_bfloat162 p0 = __floats2bfloat162_rn(y[0], y[1]);
    __nv_bfloat162 p1 = __floats2bfloat162_rn(y[2], y[3]);
    __nv_bfloat162 p2 = __floats2bfloat162_rn(y[4], y[5]);
    __nv_bfloat162 p3 = __floats2bfloat162_rn(y[6], y[7]);
    uint4 pk;
    pk.x = *(uint32_t*)&p0; pk.y = *(uint32_t*)&p1; pk.z = *(uint32_t*)&p2; pk.w = *(uint32_t*)&p3;
    *(uint4*)((char*)out + swz_off(orow, lane * 8, 256)) = pk;
}

// ---------------- bf16 TN GEMM with cp.async.bulk tile loads ----------------
// Tile 128x128, 8 warps (4M x 2N), warp tile 32x64, 3-stage ring, 2 CTAs/SM.
// A and B are swizzled 16KB tile images in gmem; one bulk copy per tile per stage.
// EPI 0: qkv  (+bias -> bf16 LINEAR out, stride 768)
// EPI 1: proj (+bias, +residual gather x[win_to_orig] -> fp32 x1 linear, window order)
// EPI 2: fc1  (+bias, GELU -> bf16 SWIZZLED out, K=1024 image)
// EPI 3: fc2  (+bias, +residual x1(win) -> fp32 out scattered to orig order)
#define STG 32768            // A 16KB + B 16KB per stage
#define GSMEM (3 * STG + 64) // + mbarriers

template<int N, int K, int EPI>
__global__ __launch_bounds__(256, 2) void gemm_kernel(const __nv_bfloat16* __restrict__ A,
                                                      const __nv_bfloat16* __restrict__ Bw,
                                                      const float* __restrict__ bias,
                                                      const float* __restrict__ res,
                                                      float* __restrict__ outf,
                                                      __nv_bfloat16* __restrict__ outb) {
    extern __shared__ __align__(128) uint8_t dynsm[];
    const int tid = threadIdx.x;
    const int lane = tid & 31;
    const int wid = tid >> 5;
    const int wm = wid & 3;      // 4 warps along M (32 rows each)
    const int wn = wid >> 2;     // 2 warps along N (64 cols each)
    const int m0 = blockIdx.x * 128;
    const int n0 = blockIdx.y * 128;
    const uint32_t sbase = smem_u32(dynsm);
    const uint32_t mb = sbase + 3 * STG;
    constexpr int KT = K / 64;

    if (tid == 0) {
        mbar_init(mb, 1); mbar_init(mb + 8, 1); mbar_init(mb + 16, 1);
    }
    __syncthreads();

    auto issue = [&](int kt) {
        uint32_t s = (uint32_t)(kt % 3);
        uint32_t mbs = mb + s * 8;
        mbar_expect_tx(mbs, 32768u);
        const char* srcA = (const char*)A + ((size_t)blockIdx.x * KT + kt) * 16384;
        const char* srcB = (const char*)Bw + ((size_t)blockIdx.y * KT + kt) * 16384;
        bulk_g2s(sbase + s * STG, srcA, 16384u, mbs);
        bulk_g2s(sbase + s * STG + 16384u, srcB, 16384u, mbs);
    };
    if (tid == 0) { issue(0); issue(1); }

    float acc[2][8][4];
#pragma unroll
    for (int a = 0; a < 2; a++)
#pragma unroll
        for (int bq = 0; bq < 8; bq++)
#pragma unroll
            for (int c = 0; c < 4; c++) acc[a][bq][c] = 0.f;

    const int ti = lane >> 3, rr = lane & 7;
#pragma unroll 1
    for (int kt = 0; kt < KT; kt++) {
        __syncthreads();
        if (tid == 0 && kt + 2 < KT) issue(kt + 2);
        mbar_wait(mb + (uint32_t)(kt % 3) * 8, (uint32_t)((kt / 3) & 1));
        uint32_t abase = sbase + (uint32_t)(kt % 3) * STG;
        uint32_t bbase = abase + 16384;
#pragma unroll
        for (int ks = 0; ks < 4; ks++) {
            int kcb = ks * 2;
            uint32_t afr[2][4];
#pragma unroll
            for (int mt = 0; mt < 2; mt++) {
                int row = wm * 32 + mt * 16 + ((ti & 1) ? 8 : 0) + rr;
                int kc = kcb + (ti >> 1);
                uint32_t addr = abase + ((((uint32_t)row << 3) | (uint32_t)(kc ^ (row & 7))) << 4);
                ldmatrix_x4(afr[mt][0], afr[mt][1], afr[mt][2], afr[mt][3], addr);
            }
            uint32_t bfr[8][2];
#pragma unroll
            for (int ng = 0; ng < 4; ng++) {
                int row = wn * 64 + ng * 16 + ((ti >> 1) ? 8 : 0) + rr;
                int kc = kcb + (ti & 1);
                uint32_t addr = bbase + ((((uint32_t)row << 3) | (uint32_t)(kc ^ (row & 7))) << 4);
                uint32_t r0, r1, r2, r3;
                ldmatrix_x4(r0, r1, r2, r3, addr);
                bfr[2 * ng][0] = r0;     bfr[2 * ng][1] = r1;
                bfr[2 * ng + 1][0] = r2; bfr[2 * ng + 1][1] = r3;
            }
#pragma unroll
            for (int mt = 0; mt < 2; mt++)
#pragma unroll
                for (int nt = 0; nt < 8; nt++)
                    mma_bf16(acc[mt][nt], afr[mt], bfr[nt]);
        }
    }

    // -------- epilogue --------
    int lrow = lane >> 2, lc2 = (lane & 3) * 2;
#pragma unroll
    for (int mt = 0; mt < 2; mt++) {
#pragma unroll
        for (int hh = 0; hh < 2; hh++) {
            int r = m0 + wm * 32 + mt * 16 + lrow + hh * 8;
            if constexpr (EPI == 0) {
                __nv_bfloat16* op = outb + (size_t)r * N;
#pragma unroll
                for (int nt = 0; nt < 8; nt++) {
                    int c = n0 + wn * 64 + nt * 8 + lc2;
                    float2 bb = *(const float2*)(bias + c);
                    *(__nv_bfloat162*)(op + c) =
                        __floats2bfloat162_rn(acc[mt][nt][2 * hh + 0] + bb.x,
                                              acc[mt][nt][2 * hh + 1] + bb.y);
                }
            } else if constexpr (EPI == 2) {
#pragma unroll
                for (int nt = 0; nt < 8; nt++) {
                    int c = n0 + wn * 64 + nt * 8 + lc2;
                    float2 bb = *(const float2*)(bias + c);
                    float v0 = gelu_f(acc[mt][nt][2 * hh + 0] + bb.x);
                    float v1 = gelu_f(acc[mt][nt][2 * hh + 1] + bb.y);
                    *(__nv_bfloat162*)((char*)outb + swz_off(r, c, 1024)) =
                        __floats2bfloat162_rn(v0, v1);
                }
            } else if constexpr (EPI == 1) {
                int torig = win_to_orig(r);
                const float* xr = res + (size_t)torig * 256;
                float* op = outf + (size_t)r * 256;
#pragma unroll
                for (int nt = 0; nt < 8; nt++) {
                    int c = n0 + wn * 64 + nt * 8 + lc2;
                    float2 bb = *(const float2*)(bias + c);
                    float2 xres = *(const float2*)(xr + c);
                    *(float2*)(op + c) = make_float2(xres.x + acc[mt][nt][2 * hh + 0] + bb.x,
                                                     xres.y + acc[mt][nt][2 * hh + 1] + bb.y);
                }
            } else {
                int torig = win_to_orig(r);
                const float* x1r = res + (size_t)r * 256;
                float* op = outf + (size_t)torig * 256;
#pragma unroll
                for (int nt = 0; nt < 8; nt++) {
                    int c = n0 + wn * 64 + nt * 8 + lc2;
                    float2 bb = *(const float2*)(bias + c);
                    float v0 = acc[mt][nt][2 * hh + 0] + bb.x;
                    float v1 = acc[mt][nt][2 * hh + 1] + bb.y;
                    float2 rr2 = *(const float2*)(x1r + c);
                    *(float2*)(op + c) = make_float2(rr2.x + v0, rr2.y + v1);
                }
            }
        }
    }
}

// ---------------- windowed attention: 1 CTA/window, warp=head; swizzled out ----------------
#define ATT_PITCH 1552
#define ATT_SMEM (64 * ATT_PITCH)

__global__ __launch_bounds__(256, 2) void attn_kernel(const __nv_bfloat16* __restrict__ qkv,
                                                      const float* __restrict__ bias_pre,
                                                      __nv_bfloat16* __restrict__ out) {
    extern __shared__ __align__(128) uint8_t dynsm[];
    const int w = blockIdx.x;
    const int tid = threadIdx.x;
    const int h = tid >> 5, lane = tid & 31;
    const uint32_t sb = smem_u32(dynsm);
    const __nv_bfloat16* gw = qkv + (size_t)w * 49152;

#pragma unroll
    for (int i = 0; i < 24; i++) {
        int ch = tid + i * 256;
        int r = ch / 96, c = ch % 96;
        cp_async16(sb + (uint32_t)(r * ATT_PITCH + c * 16), gw + r * 768 + c * 8);
    }
    cp_commit();
    asm volatile("cp.async.wait_group 0;\n" ::: "memory");
    __syncthreads();

    const uint32_t qbase = sb + (uint32_t)(h * 32) * 2;
    const uint32_t kbase = sb + (uint32_t)(256 + h * 32) * 2;
    const uint32_t vbase = sb + (uint32_t)(512 + h * 32) * 2;
    const float* bp = bias_pre + h * 4096;
    const float scale = 0.17677669529663688f;
    const int ti = lane >> 3, rr = lane & 7;
    const int lq = lane >> 2, lc = (lane & 3) * 2;

#pragma unroll 1
    for (int i = 0; i < 4; i++) {
        uint32_t qf[2][4];
#pragma unroll
        for (int ks = 0; ks < 2; ks++) {
            int row = i * 16 + ((ti & 1) ? 8 : 0) + rr;
            uint32_t addr = qbase + (uint32_t)(row * ATT_PITCH) + (uint32_t)((ks * 2 + (ti >> 1)) * 16);
            ldmatrix_x4(qf[ks][0], qf[ks][1], qf[ks][2], qf[ks][3], addr);
        }
        float sacc[8][4];
#pragma unroll
        for (int j = 0; j < 8; j++)
#pragma unroll
            for (int c = 0; c < 4; c++) sacc[j][c] = 0.f;
#pragma unroll
        for (int ks = 0; ks < 2; ks++) {
#pragma unroll
            for (int ng = 0; ng < 4; ng++) {
                int row = ng * 16 + ((ti >> 1) ? 8 : 0) + rr;
                uint32_t addr = kbase + (uint32_t)(row * ATT_PITCH) + (uint32_t)((ks * 2 + (ti & 1)) * 16);
                uint32_t b0, b1, b2, b3;
                ldmatrix_x4(b0, b1, b2, b3, addr);
                uint32_t bf0[2] = { b0, b1 }, bf1[2] = { b2, b3 };
                mma_bf16(sacc[2 * ng],     qf[ks], bf0);
                mma_bf16(sacc[2 * ng + 1], qf[ks], bf1);
            }
        }
        int r0 = i * 16 + lq, r1 = r0 + 8;
        float p[8][4];
        float mx0 = -1e30f, mx1 = -1e30f;
#pragma unroll
        for (int j = 0; j < 8; j++) {
            float2 b0 = *(const float2*)(bp + r0 * 64 + j * 8 + lc);
            float2 b1 = *(const float2*)(bp + r1 * 64 + j * 8 + lc);
            p[j][0] = fmaf(sacc[j][0], scale, b0.x);
            p[j][1] = fmaf(sacc[j][1], scale, b0.y);
            p[j][2] = fmaf(sacc[j][2], scale, b1.x);
            p[j][3] = fmaf(sacc[j][3], scale, b1.y);
            mx0 = fmaxf(mx0, fmaxf(p[j][0], p[j][1]));
            mx1 = fmaxf(mx1, fmaxf(p[j][2], p[j][3]));
        }
        mx0 = fmaxf(mx0, __shfl_xor_sync(0xffffffffu, mx0, 1));
        mx0 = fmaxf(mx0, __shfl_xor_sync(0xffffffffu, mx0, 2));
        mx1 = fmaxf(mx1, __shfl_xor_sync(0xffffffffu, mx1, 1));
        mx1 = fmaxf(mx1, __shfl_xor_sync(0xffffffffu, mx1, 2));
        float sm0 = 0.f, sm1 = 0.f;
#pragma unroll
        for (int j = 0; j < 8; j++) {
            p[j][0] = __expf(p[j][0] - mx0);
            p[j][1] = __expf(p[j][1] - mx0);
            p[j][2] = __expf(p[j][2] - mx1);
            p[j][3] = __expf(p[j][3] - mx1);
            sm0 += p[j][0] + p[j][1];
            sm1 += p[j][2] + p[j][3];
        }
        sm0 += __shfl_xor_sync(0xffffffffu, sm0, 1);
        sm0 += __shfl_xor_sync(0xffffffffu, sm0, 2);
        sm1 += __shfl_xor_sync(0xffffffffu, sm1, 1);
        sm1 += __shfl_xor_sync(0xffffffffu, sm1, 2);
        float inv0 = 1.0f / sm0, inv1 = 1.0f / sm1;

        uint32_t ap[4][4];
#pragma unroll
        for (int ks = 0; ks < 4; ks++) {
            __nv_bfloat162 t0 = __floats2bfloat162_rn(p[2 * ks][0],     p[2 * ks][1]);
            __nv_bfloat162 t1 = __floats2bfloat162_rn(p[2 * ks][2],     p[2 * ks][3]);
            __nv_bfloat162 t2 = __floats2bfloat162_rn(p[2 * ks + 1][0], p[2 * ks + 1][1]);
            __nv_bfloat162 t3 = __floats2bfloat162_rn(p[2 * ks + 1][2], p[2 * ks + 1][3]);
            ap[ks][0] = *(uint32_t*)&t0; ap[ks][1] = *(uint32_t*)&t1;
            ap[ks][2] = *(uint32_t*)&t2; ap[ks][3] = *(uint32_t*)&t3;
        }
        float o[4][4];
#pragma unroll
        for (int jj = 0; jj < 4; jj++)
#pragma unroll
            for (int c = 0; c < 4; c++) o[jj][c] = 0.f;
#pragma unroll
        for (int ks = 0; ks < 4; ks++) {
#pragma unroll
            for (int jj = 0; jj < 4; jj++) {
                uint32_t bv[2];
                uint32_t addr = vbase + (uint32_t)((ks * 16 + (lane & 15)) * ATT_PITCH) + (uint32_t)(jj * 16);
                ldmatrix_x2_trans(bv[0], bv[1], addr);
                mma_bf16(o[jj], ap[ks], bv);
            }
        }
        // swizzled output (g_attn is proj's GEMM-A, K=256)
        int row0 = w * 64 + r0, row1 = w * 64 + r1;
#pragma unroll
        for (int jj = 0; jj < 4; jj++) {
            int k = h * 32 + jj * 8 + lc;
            *(__nv_bfloat162*)((char*)out + swz_off(row0, k, 256)) =
                __floats2bfloat162_rn(o[jj][0] * inv0, o[jj][1] * inv0);
            *(__nv_bfloat162*)((char*)out + swz_off(row1, k, 256)) =
                __floats2bfloat162_rn(o[jj][2] * inv1, o[jj][3] * inv1);
        }
    }
}

// ---------------- launch ----------------
extern "C" void kernel_launch(void* const* d_in, const int* in_sizes, int n_in,
                              void* d_out, int out_size) {
    const float* x      = (const float*)d_in[0];
    const float* g1     = (const float*)d_in[2];
    const float* b1     = (const float*)d_in[3];
    const float* w_qkv  = (const float*)d_in[4];
    const float* b_qkv  = (const float*)d_in[5];
    const float* btab   = (const float*)d_in[6];
    const float* w_proj = (const float*)d_in[7];
    const float* b_proj = (const float*)d_in[8];
    const float* g2     = (const float*)d_in[9];
    const float* b2     = (const float*)d_in[10];
    const float* w_fc1  = (const float*)d_in[11];
    const float* b_fc1  = (const float*)d_in[12];
    const float* w_fc2  = (const float*)d_in[13];
    const float* b_fc2  = (const float*)d_in[14];
    float* out = (float*)d_out;

    __nv_bfloat16 *xw, *qkv, *attn, *xn2, *hbuf, *wall;
    float *x1, *bpre;
    cudaGetSymbolAddress((void**)&xw,   g_xw);
    cudaGetSymbolAddress((void**)&qkv,  g_qkv);
    cudaGetSymbolAddress((void**)&attn, g_attn);
    cudaGetSymbolAddress((void**)&x1,   g_x1);
    cudaGetSymbolAddress((void**)&xn2,  g_xn2);
    cudaGetSymbolAddress((void**)&hbuf, g_h);
    cudaGetSymbolAddress((void**)&wall, g_wall);
    cudaGetSymbolAddress((void**)&bpre, g_bias);

    __nv_bfloat16* wq = wall + WOFF_QKV;
    __nv_bfloat16* wp = wall + WOFF_PROJ;
    __nv_bfloat16* w1 = wall + WOFF_FC1;
    __nv_bfloat16* w2 = wall + WOFF_FC2;

    cudaFuncSetAttribute(gemm_kernel<768, 256, 0>,  cudaFuncAttributeMaxDynamicSharedMemorySize, GSMEM);
    cudaFuncSetAttribute(gemm_kernel<256, 256, 1>,  cudaFuncAttributeMaxDynamicSharedMemorySize, GSMEM);
    cudaFuncSetAttribute(gemm_kernel<1024, 256, 2>, cudaFuncAttributeMaxDynamicSharedMemorySize, GSMEM);
    cudaFuncSetAttribute(gemm_kernel<256, 1024, 3>, cudaFuncAttributeMaxDynamicSharedMemorySize, GSMEM);
    cudaFuncSetAttribute(attn_kernel, cudaFuncAttributeMaxDynamicSharedMemorySize, ATT_SMEM);

    cvt_all_kernel<<<WTOT / 8 / 256, 256>>>(w_qkv, w_proj, w_fc1, w_fc2, wall);
    bias_kernel<<<HEADS * 64 * 64 / 256, 256>>>(btab, bpre);
    ln_kernel<1><<<TTOK / 8, 256>>>(x, g1, b1, xw);
    gemm_kernel<768, 256, 0><<<dim3(TTOK / 128, 6), 256, GSMEM>>>(
        xw, wq, b_qkv, nullptr, nullptr, qkv);
    attn_kernel<<<2048, 256, ATT_SMEM>>>(qkv, bpre, attn);
    gemm_kernel<256, 256, 1><<<dim3(TTOK / 128, 2), 256, GSMEM>>>(
        attn, wp, b_proj, x, x1, nullptr);
    ln_kernel<0><<<TTOK / 8, 256>>>(x1, g2, b2, xn2);
    gemm_kernel<1024, 256, 2><<<dim3(TTOK / 128, 8), 256, GSMEM>>>(
        xn2, w1, b_fc1, nullptr, nullptr, hbuf);
    gemm_kernel<256, 1024, 3><<<dim3(TTOK / 128, 2), 256, GSMEM>>>(
        hbuf, w2, b_fc2, x1, out, nullptr);
}

// round 11
// speedup vs baseline: 1.0565x; 1.0499x over previous
#include <cuda_runtime.h>
#include <cuda_fp16.h>
#include <math.h>
#include <stdint.h>

#define DIMC 256
#define HEADS 8
#define TTOK 131072          // 32*4096 tokens
#define HIDD 1024

// ---------------- scratch (static __device__, no allocs) ----------------
// GEMM-A activations + weights live as swizzled 16KB tile images:
//   tile index = (row>>7)*(K/64) + (k>>6); within tile:
//   byte = (row&127)*128 + ((((k&63)>>3) ^ (row&7))<<4) + (k&7)*2
__device__ __align__(128) __half g_xw  [(size_t)TTOK * DIMC];     // swizzled, K=256
__device__ __align__(128) __half g_qkv [(size_t)TTOK * 3 * DIMC]; // LINEAR (attn input)
__device__ __align__(128) __half g_attn[(size_t)TTOK * DIMC];     // swizzled, K=256
__device__ __align__(128) float  g_x1  [(size_t)TTOK * DIMC];     // linear fp32, window order
__device__ __align__(128) __half g_xn2 [(size_t)TTOK * DIMC];     // swizzled, K=256
__device__ __align__(128) __half g_h   [(size_t)TTOK * HIDD];     // swizzled, K=1024
__device__ __align__(128) __half g_wall[(3 * DIMC + DIMC + HIDD + DIMC) * DIMC + DIMC * HIDD]; // swizzled
__device__ float g_bias[HEADS * 64 * 64];

#define WOFF_QKV  0
#define WOFF_PROJ (3 * DIMC * DIMC)
#define WOFF_FC1  (WOFF_PROJ + DIMC * DIMC)
#define WOFF_FC2  (WOFF_FC1 + HIDD * DIMC)
#define WTOT      (WOFF_FC2 + DIMC * HIDD)

// ---------------- helpers ----------------
__device__ __forceinline__ uint32_t smem_u32(const void* p) {
    return (uint32_t)__cvta_generic_to_shared(p);
}
__device__ __forceinline__ void cp_async16(uint32_t saddr, const void* gptr) {
    asm volatile("cp.async.cg.shared.global [%0], [%1], 16;\n" :: "r"(saddr), "l"(gptr));
}
__device__ __forceinline__ void cp_commit() { asm volatile("cp.async.commit_group;\n"); }
__device__ __forceinline__ void bulk_g2s(uint32_t dst, const void* src, uint32_t bytes, uint32_t mbar) {
    asm volatile("cp.async.bulk.shared::cluster.global.mbarrier::complete_tx::bytes [%0], [%1], %2, [%3];"
                 :: "r"(dst), "l"(src), "r"(bytes), "r"(mbar) : "memory");
}
__device__ __forceinline__ void mbar_init(uint32_t mbar, uint32_t cnt) {
    asm volatile("mbarrier.init.shared.b64 [%0], %1;" :: "r"(mbar), "r"(cnt) : "memory");
}
__device__ __forceinline__ void mbar_expect_tx(uint32_t mbar, uint32_t bytes) {
    asm volatile("mbarrier.arrive.expect_tx.shared.b64 _, [%0], %1;" :: "r"(mbar), "r"(bytes) : "memory");
}
__device__ __forceinline__ void mbar_wait(uint32_t mbar, uint32_t parity) {
    asm volatile("{\n\t.reg .pred P1;\n\t"
                 "WAIT_%=:\n\t"
                 "mbarrier.try_wait.parity.acquire.cta.shared::cta.b64 P1, [%0], %1, 0x989680;\n\t"
                 "@P1 bra.uni DONE_%=;\n\t"
                 "bra.uni WAIT_%=;\n\t"
                 "DONE_%=:\n\t}"
                 :: "r"(mbar), "r"(parity) : "memory");
}
__device__ __forceinline__ void ldmatrix_x4(uint32_t& r0, uint32_t& r1, uint32_t& r2, uint32_t& r3, uint32_t addr) {
    asm volatile("ldmatrix.sync.aligned.m8n8.x4.shared.b16 {%0,%1,%2,%3}, [%4];\n"
                 : "=r"(r0), "=r"(r1), "=r"(r2), "=r"(r3) : "r"(addr));
}
__device__ __forceinline__ void ldmatrix_x2_trans(uint32_t& r0, uint32_t& r1, uint32_t addr) {
    asm volatile("ldmatrix.sync.aligned.m8n8.x2.trans.shared.b16 {%0,%1}, [%2];\n"
                 : "=r"(r0), "=r"(r1) : "r"(addr));
}
// f16-accumulator HMMA (full-rate path): D(f16x4) = A(f16) B(f16) + C(f16x4)
__device__ __forceinline__ void mma_f16acc(uint32_t c[2], const uint32_t a[4], const uint32_t b[2]) {
    asm volatile("mma.sync.aligned.m16n8k16.row.col.f16.f16.f16.f16 "
                 "{%0,%1}, {%2,%3,%4,%5}, {%6,%7}, {%0,%1};\n"
                 : "+r"(c[0]), "+r"(c[1])
                 : "r"(a[0]), "r"(a[1]), "r"(a[2]), "r"(a[3]), "r"(b[0]), "r"(b[1]));
}
// f32-accumulator HMMA with fp16 inputs (attention)
__device__ __forceinline__ void mma_f32acc(float c[4], const uint32_t a[4], const uint32_t b[2]) {
    asm volatile("mma.sync.aligned.m16n8k16.row.col.f32.f16.f16.f32 "
                 "{%0,%1,%2,%3}, {%4,%5,%6,%7}, {%8,%9}, {%0,%1,%2,%3};\n"
                 : "+f"(c[0]), "+f"(c[1]), "+f"(c[2]), "+f"(c[3])
                 : "r"(a[0]), "r"(a[1]), "r"(a[2]), "r"(a[3]), "r"(b[0]), "r"(b[1]));
}
__device__ __forceinline__ float gelu_f(float v) {
    return 0.5f * v * (1.0f + erff(v * 0.7071067811865476f));
}
__device__ __forceinline__ int orig_to_win(int t) {
    int b = t >> 12, rem = t & 4095;
    int r = rem >> 6, c = rem & 63;
    int wi = (b << 6) + ((r >> 3) << 3) + (c >> 3);
    return (wi << 6) + ((r & 7) << 3) + (c & 7);
}
__device__ __forceinline__ int win_to_orig(int tw) {
    int wi = tw >> 6, k = tw & 63;
    int b = wi >> 6, w64 = wi & 63;
    int r = ((w64 >> 3) << 3) + (k >> 3);
    int c = ((w64 & 7) << 3) + (k & 7);
    return (b << 12) + (r << 6) + c;
}
__device__ __forceinline__ size_t swz_off(int row, int k, int Kd) {
    return ((size_t)((row >> 7) * (Kd >> 6) + (k >> 6)) << 14)
         + (size_t)((row & 127) * 128 + ((((k & 63) >> 3) ^ (row & 7)) << 4) + (k & 7) * 2);
}

// ---------------- fused weight convert -> swizzled fp16 tiles ----------------
__global__ void cvt_all_kernel(const float* __restrict__ wqkv, const float* __restrict__ wproj,
                               const float* __restrict__ wfc1, const float* __restrict__ wfc2,
                               __half* __restrict__ out) {
    int i = blockIdx.x * blockDim.x + threadIdx.x;
    int li = i * 8;
    const float* src; size_t basebyte; int Kd; int loc;
    if (li < WOFF_PROJ)      { src = wqkv;  loc = li;             basebyte = 0;                    Kd = 256; }
    else if (li < WOFF_FC1)  { src = wproj; loc = li - WOFF_PROJ; basebyte = (size_t)WOFF_PROJ*2;  Kd = 256; }
    else if (li < WOFF_FC2)  { src = wfc1;  loc = li - WOFF_FC1;  basebyte = (size_t)WOFF_FC1*2;   Kd = 256; }
    else                     { src = wfc2;  loc = li - WOFF_FC2;  basebyte = (size_t)WOFF_FC2*2;   Kd = 1024; }
    float4 a = *(const float4*)(src + loc);
    float4 b = *(const float4*)(src + loc + 4);
    int row = loc / Kd, k = loc % Kd;
    size_t off = basebyte + swz_off(row, k, Kd);
    __half2 p0 = __floats2half2_rn(a.x, a.y);
    __half2 p1 = __floats2half2_rn(a.z, a.w);
    __half2 p2 = __floats2half2_rn(b.x, b.y);
    __half2 p3 = __floats2half2_rn(b.z, b.w);
    uint4 pk;
    pk.x = *(uint32_t*)&p0; pk.y = *(uint32_t*)&p1; pk.z = *(uint32_t*)&p2; pk.w = *(uint32_t*)&p3;
    *(uint4*)((char*)out + off) = pk;
}

// ---------------- bias table precompute: g_bias[h][n][m] ----------------
__global__ void bias_kernel(const float* __restrict__ btab, float* __restrict__ bout) {
    int t = blockIdx.x * blockDim.x + threadIdx.x;
    int m = t & 63, n = (t >> 6) & 63, h = t >> 12;
    int rel = ((n >> 3) - (m >> 3) + 7) * 15 + ((n & 7) - (m & 7) + 7);
    bout[t] = btab[rel * 8 + h];
}

// ---------------- LayerNorm (warp per token) -> swizzled fp16 out (K=256) ----------------
template<int PERM>
__global__ __launch_bounds__(256) void ln_kernel(const float* __restrict__ x,
                                                 const float* __restrict__ g,
                                                 const float* __restrict__ b,
                                                 __half* __restrict__ out) {
    int warp = (blockIdx.x * 256 + threadIdx.x) >> 5;
    int lane = threadIdx.x & 31;
    const float* row = x + (size_t)warp * DIMC + lane * 8;
    float4 v0 = *(const float4*)row;
    float4 v1 = *(const float4*)(row + 4);
    float s = (v0.x + v0.y) + (v0.z + v0.w) + ((v1.x + v1.y) + (v1.z + v1.w));
#pragma unroll
    for (int o = 16; o; o >>= 1) s += __shfl_xor_sync(0xffffffffu, s, o);
    float mu = s * (1.0f / 256.0f);
    float d[8] = { v0.x - mu, v0.y - mu, v0.z - mu, v0.w - mu,
                   v1.x - mu, v1.y - mu, v1.z - mu, v1.w - mu };
    float ss = 0.f;
#pragma unroll
    for (int i = 0; i < 8; i++) ss += d[i] * d[i];
#pragma unroll
    for (int o = 16; o; o >>= 1) ss += __shfl_xor_sync(0xffffffffu, ss, o);
    float rstd = rsqrtf(ss * (1.0f / 256.0f) + 1e-5f);
    float4 gg0 = *(const float4*)(g + lane * 8);
    float4 gg1 = *(const float4*)(g + lane * 8 + 4);
    float4 bb0 = *(const float4*)(b + lane * 8);
    float4 bb1 = *(const float4*)(b + lane * 8 + 4);
    float y[8];
    y[0] = d[0] * rstd * gg0.x + bb0.x;  y[1] = d[1] * rstd * gg0.y + bb0.y;
    y[2] = d[2] * rstd * gg0.z + bb0.z;  y[3] = d[3] * rstd * gg0.w + bb0.w;
    y[4] = d[4] * rstd * gg1.x + bb1.x;  y[5] = d[5] * rstd * gg1.y + bb1.y;
    y[6] = d[6] * rstd * gg1.z + bb1.z;  y[7] = d[7] * rstd * gg1.w + bb1.w;
    int orow = PERM ? orig_to_win(warp) : warp;
    __half2 p0 = __floats2half2_rn(y[0], y[1]);
    __half2 p1 = __floats2half2_rn(y[2], y[3]);
    __half2 p2 = __floats2half2_rn(y[4], y[5]);
    __half2 p3 = __floats2half2_rn(y[6], y[7]);
    uint4 pk;
    pk.x = *(uint32_t*)&p0; pk.y = *(uint32_t*)&p1; pk.z = *(uint32_t*)&p2; pk.w = *(uint32_t*)&p3;
    *(uint4*)((char*)out + swz_off(orow, lane * 8, 256)) = pk;
}

// ---------------- fp16 TN GEMM (f16 accumulate) with cp.async.bulk tile loads ----------------
// Tile 128x128, 8 warps (4M x 2N), warp tile 32x64, 3-stage ring, 2 CTAs/SM.
// EPI 0: qkv  (+bias -> fp16 LINEAR out, stride 768)
// EPI 1: proj (+bias, +residual gather x[win_to_orig] -> fp32 x1 linear, window order)
// EPI 2: fc1  (+bias, GELU -> fp16 SWIZZLED out, K=1024 image)
// EPI 3: fc2  (+bias, +residual x1(win) -> fp32 out scattered to orig order)
#define STG 32768
#define GSMEM (3 * STG + 64)

template<int N, int K, int EPI>
__global__ __launch_bounds__(256, 2) void gemm_kernel(const __half* __restrict__ A,
                                                      const __half* __restrict__ Bw,
                                                      const float* __restrict__ bias,
                                                      const float* __restrict__ res,
                                                      float* __restrict__ outf,
                                                      __half* __restrict__ outb) {
    extern __shared__ __align__(128) uint8_t dynsm[];
    const int tid = threadIdx.x;
    const int lane = tid & 31;
    const int wid = tid >> 5;
    const int wm = wid & 3;
    const int wn = wid >> 2;
    const int m0 = blockIdx.x * 128;
    const int n0 = blockIdx.y * 128;
    const uint32_t sbase = smem_u32(dynsm);
    const uint32_t mb = sbase + 3 * STG;
    constexpr int KT = K / 64;

    if (tid == 0) {
        mbar_init(mb, 1); mbar_init(mb + 8, 1); mbar_init(mb + 16, 1);
    }
    __syncthreads();

    auto issue = [&](int kt) {
        uint32_t s = (uint32_t)(kt % 3);
        uint32_t mbs = mb + s * 8;
        mbar_expect_tx(mbs, 32768u);
        const char* srcA = (const char*)A + ((size_t)blockIdx.x * KT + kt) * 16384;
        const char* srcB = (const char*)Bw + ((size_t)blockIdx.y * KT + kt) * 16384;
        bulk_g2s(sbase + s * STG, srcA, 16384u, mbs);
        bulk_g2s(sbase + s * STG + 16384u, srcB, 16384u, mbs);
    };
    if (tid == 0) { issue(0); issue(1); }

    uint32_t acc[2][8][2];   // f16x2 accumulators
#pragma unroll
    for (int a = 0; a < 2; a++)
#pragma unroll
        for (int bq = 0; bq < 8; bq++) { acc[a][bq][0] = 0u; acc[a][bq][1] = 0u; }

    const int ti = lane >> 3, rr = lane & 7;
#pragma unroll 1
    for (int kt = 0; kt < KT; kt++) {
        __syncthreads();
        if (tid == 0 && kt + 2 < KT) issue(kt + 2);
        mbar_wait(mb + (uint32_t)(kt % 3) * 8, (uint32_t)((kt / 3) & 1));
        uint32_t abase = sbase + (uint32_t)(kt % 3) * STG;
        uint32_t bbase = abase + 16384;
#pragma unroll
        for (int ks = 0; ks < 4; ks++) {
            int kcb = ks * 2;
            uint32_t afr[2][4];
#pragma unroll
            for (int mt = 0; mt < 2; mt++) {
                int row = wm * 32 + mt * 16 + ((ti & 1) ? 8 : 0) + rr;
                int kc = kcb + (ti >> 1);
                uint32_t addr = abase + ((((uint32_t)row << 3) | (uint32_t)(kc ^ (row & 7))) << 4);
                ldmatrix_x4(afr[mt][0], afr[mt][1], afr[mt][2], afr[mt][3], addr);
            }
            uint32_t bfr[8][2];
#pragma unroll
            for (int ng = 0; ng < 4; ng++) {
                int row = wn * 64 + ng * 16 + ((ti >> 1) ? 8 : 0) + rr;
                int kc = kcb + (ti & 1);
                uint32_t addr = bbase + ((((uint32_t)row << 3) | (uint32_t)(kc ^ (row & 7))) << 4);
                uint32_t r0, r1, r2, r3;
                ldmatrix_x4(r0, r1, r2, r3, addr);
                bfr[2 * ng][0] = r0;     bfr[2 * ng][1] = r1;
                bfr[2 * ng + 1][0] = r2; bfr[2 * ng + 1][1] = r3;
            }
#pragma unroll
            for (int mt = 0; mt < 2; mt++)
#pragma unroll
                for (int nt = 0; nt < 8; nt++)
                    mma_f16acc(acc[mt][nt], afr[mt], bfr[nt]);
        }
    }

    // -------- epilogue (promote f16 acc -> f32) --------
    int lrow = lane >> 2, lc2 = (lane & 3) * 2;
#pragma unroll
    for (int mt = 0; mt < 2; mt++) {
#pragma unroll
        for (int hh = 0; hh < 2; hh++) {
            int r = m0 + wm * 32 + mt * 16 + lrow + hh * 8;
            if constexpr (EPI == 0) {
                __half* op = outb + (size_t)r * N;
#pragma unroll
                for (int nt = 0; nt < 8; nt++) {
                    int c = n0 + wn * 64 + nt * 8 + lc2;
                    float2 bb = *(const float2*)(bias + c);
                    float2 cv = __half22float2(*(__half2*)&acc[mt][nt][hh]);
                    *(__half2*)(op + c) = __floats2half2_rn(cv.x + bb.x, cv.y + bb.y);
                }
            } else if constexpr (EPI == 2) {
#pragma unroll
                for (int nt = 0; nt < 8; nt++) {
                    int c = n0 + wn * 64 + nt * 8 + lc2;
                    float2 bb = *(const float2*)(bias + c);
                    float2 cv = __half22float2(*(__half2*)&acc[mt][nt][hh]);
                    *(__half2*)((char*)outb + swz_off(r, c, 1024)) =
                        __floats2half2_rn(gelu_f(cv.x + bb.x), gelu_f(cv.y + bb.y));
                }
            } else if constexpr (EPI == 1) {
                int torig = win_to_orig(r);
                const float* xr = res + (size_t)torig * 256;
                float* op = outf + (size_t)r * 256;
#pragma unroll
                for (int nt = 0; nt < 8; nt++) {
                    int c = n0 + wn * 64 + nt * 8 + lc2;
                    float2 bb = *(const float2*)(bias + c);
                    float2 cv = __half22float2(*(__half2*)&acc[mt][nt][hh]);
                    float2 xres = *(const float2*)(xr + c);
                    *(float2*)(op + c) = make_float2(xres.x + cv.x + bb.x, xres.y + cv.y + bb.y);
                }
            } else {
                int torig = win_to_orig(r);
                const float* x1r = res + (size_t)r * 256;
                float* op = outf + (size_t)torig * 256;
#pragma unroll
                for (int nt = 0; nt < 8; nt++) {
                    int c = n0 + wn * 64 + nt * 8 + lc2;
                    float2 bb = *(const float2*)(bias + c);
                    float2 cv = __half22float2(*(__half2*)&acc[mt][nt][hh]);
                    float2 rr2 = *(const float2*)(x1r + c);
                    *(float2*)(op + c) = make_float2(rr2.x + cv.x + bb.x, rr2.y + cv.y + bb.y);
                }
            }
        }
    }
}

// ---------------- windowed attention: fp16 inputs, f32 accum; swizzled fp16 out ----------------
#define ATT_PITCH 1552
#define ATT_SMEM (64 * ATT_PITCH)

__global__ __launch_bounds__(256, 2) void attn_kernel(const __half* __restrict__ qkv,
                                                      const float* __restrict__ bias_pre,
                                                      __half* __restrict__ out) {
    extern __shared__ __align__(128) uint8_t dynsm[];
    const int w = blockIdx.x;
    const int tid = threadIdx.x;
    const int h = tid >> 5, lane = tid & 31;
    const uint32_t sb = smem_u32(dynsm);
    const __half* gw = qkv + (size_t)w * 49152;

#pragma unroll
    for (int i = 0; i < 24; i++) {
        int ch = tid + i * 256;
        int r = ch / 96, c = ch % 96;
        cp_async16(sb + (uint32_t)(r * ATT_PITCH + c * 16), gw + r * 768 + c * 8);
    }
    cp_commit();
    asm volatile("cp.async.wait_group 0;\n" ::: "memory");
    __syncthreads();

    const uint32_t qbase = sb + (uint32_t)(h * 32) * 2;
    const uint32_t kbase = sb + (uint32_t)(256 + h * 32) * 2;
    const uint32_t vbase = sb + (uint32_t)(512 + h * 32) * 2;
    const float* bp = bias_pre + h * 4096;
    const float scale = 0.17677669529663688f;
    const int ti = lane >> 3, rr = lane & 7;
    const int lq = lane >> 2, lc = (lane & 3) * 2;

#pragma unroll 1
    for (int i = 0; i < 4; i++) {
        uint32_t qf[2][4];
#pragma unroll
        for (int ks = 0; ks < 2; ks++) {
            int row = i * 16 + ((ti & 1) ? 8 : 0) + rr;
            uint32_t addr = qbase + (uint32_t)(row * ATT_PITCH) + (uint32_t)((ks * 2 + (ti >> 1)) * 16);
            ldmatrix_x4(qf[ks][0], qf[ks][1], qf[ks][2], qf[ks][3], addr);
        }
        float sacc[8][4];
#pragma unroll
        for (int j = 0; j < 8; j++)
#pragma unroll
            for (int c = 0; c < 4; c++) sacc[j][c] = 0.f;
#pragma unroll
        for (int ks = 0; ks < 2; ks++) {
#pragma unroll
            for (int ng = 0; ng < 4; ng++) {
                int row = ng * 16 + ((ti >> 1) ? 8 : 0) + rr;
                uint32_t addr = kbase + (uint32_t)(row * ATT_PITCH) + (uint32_t)((ks * 2 + (ti & 1)) * 16);
                uint32_t b0, b1, b2, b3;
                ldmatrix_x4(b0, b1, b2, b3, addr);
                uint32_t bf0[2] = { b0, b1 }, bf1[2] = { b2, b3 };
                mma_f32acc(sacc[2 * ng],     qf[ks], bf0);
                mma_f32acc(sacc[2 * ng + 1], qf[ks], bf1);
            }
        }
        int r0 = i * 16 + lq, r1 = r0 + 8;
        float p[8][4];
        float mx0 = -1e30f, mx1 = -1e30f;
#pragma unroll
        for (int j = 0; j < 8; j++) {
            float2 b0 = *(const float2*)(bp + r0 * 64 + j * 8 + lc);
            float2 b1 = *(const float2*)(bp + r1 * 64 + j * 8 + lc);
            p[j][0] = fmaf(sacc[j][0], scale, b0.x);
            p[j][1] = fmaf(sacc[j][1], scale, b0.y);
            p[j][2] = fmaf(sacc[j][2], scale, b1.x);
            p[j][3] = fmaf(sacc[j][3], scale, b1.y);
            mx0 = fmaxf(mx0, fmaxf(p[j][0], p[j][1]));
            mx1 = fmaxf(mx1, fmaxf(p[j][2], p[j][3]));
        }
        mx0 = fmaxf(mx0, __shfl_xor_sync(0xffffffffu, mx0, 1));
        mx0 = fmaxf(mx0, __shfl_xor_sync(0xffffffffu, mx0, 2));
        mx1 = fmaxf(mx1, __shfl_xor_sync(0xffffffffu, mx1, 1));
        mx1 = fmaxf(mx1, __shfl_xor_sync(0xffffffffu, mx1, 2));
        float sm0 = 0.f, sm1 = 0.f;
#pragma unroll
        for (int j = 0; j < 8; j++) {
            p[j][0] = __expf(p[j][0] - mx0);
            p[j][1] = __expf(p[j][1] - mx0);
            p[j][2] = __expf(p[j][2] - mx1);
            p[j][3] = __expf(p[j][3] - mx1);
            sm0 += p[j][0] + p[j][1];
            sm1 += p[j][2] + p[j][3];
        }
        sm0 += __shfl_xor_sync(0xffffffffu, sm0, 1);
        sm0 += __shfl_xor_sync(0xffffffffu, sm0, 2);
        sm1 += __shfl_xor_sync(0xffffffffu, sm1, 1);
        sm1 += __shfl_xor_sync(0xffffffffu, sm1, 2);
        float inv0 = 1.0f / sm0, inv1 = 1.0f / sm1;

        uint32_t ap[4][4];
#pragma unroll
        for (int ks = 0; ks < 4; ks++) {
            __half2 t0 = __floats2half2_rn(p[2 * ks][0],     p[2 * ks][1]);
            __half2 t1 = __floats2half2_rn(p[2 * ks][2],     p[2 * ks][3]);
            __half2 t2 = __floats2half2_rn(p[2 * ks + 1][0], p[2 * ks + 1][1]);
            __half2 t3 = __floats2half2_rn(p[2 * ks + 1][2], p[2 * ks + 1][3]);
            ap[ks][0] = *(uint32_t*)&t0; ap[ks][1] = *(uint32_t*)&t1;
            ap[ks][2] = *(uint32_t*)&t2; ap[ks][3] = *(uint32_t*)&t3;
        }
        float o[4][4];
#pragma unroll
        for (int jj = 0; jj < 4; jj++)
#pragma unroll
            for (int c = 0; c < 4; c++) o[jj][c] = 0.f;
#pragma unroll
        for (int ks = 0; ks < 4; ks++) {
#pragma unroll
            for (int jj = 0; jj < 4; jj++) {
                uint32_t bv[2];
                uint32_t addr = vbase + (uint32_t)((ks * 16 + (lane & 15)) * ATT_PITCH) + (uint32_t)(jj * 16);
                ldmatrix_x2_trans(bv[0], bv[1], addr);
                mma_f32acc(o[jj], ap[ks], bv);
            }
        }
        int row0 = w * 64 + r0, row1 = w * 64 + r1;
#pragma unroll
        for (int jj = 0; jj < 4; jj++) {
            int k = h * 32 + jj * 8 + lc;
            *(__half2*)((char*)out + swz_off(row0, k, 256)) =
                __floats2half2_rn(o[jj][0] * inv0, o[jj][1] * inv0);
            *(__half2*)((char*)out + swz_off(row1, k, 256)) =
                __floats2half2_rn(o[jj][2] * inv1, o[jj][3] * inv1);
        }
    }
}

// ---------------- launch ----------------
extern "C" void kernel_launch(void* const* d_in, const int* in_sizes, int n_in,
                              void* d_out, int out_size) {
    const float* x      = (const float*)d_in[0];
    const float* g1     = (const float*)d_in[2];
    const float* b1     = (const float*)d_in[3];
    const float* w_qkv  = (const float*)d_in[4];
    const float* b_qkv  = (const float*)d_in[5];
    const float* btab   = (const float*)d_in[6];
    const float* w_proj = (const float*)d_in[7];
    const float* b_proj = (const float*)d_in[8];
    const float* g2     = (const float*)d_in[9];
    const float* b2     = (const float*)d_in[10];
    const float* w_fc1  = (const float*)d_in[11];
    const float* b_fc1  = (const float*)d_in[12];
    const float* w_fc2  = (const float*)d_in[13];
    const float* b_fc2  = (const float*)d_in[14];
    float* out = (float*)d_out;

    __half *xw, *qkv, *attn, *xn2, *hbuf, *wall;
    float *x1, *bpre;
    cudaGetSymbolAddress((void**)&xw,   g_xw);
    cudaGetSymbolAddress((void**)&qkv,  g_qkv);
    cudaGetSymbolAddress((void**)&attn, g_attn);
    cudaGetSymbolAddress((void**)&x1,   g_x1);
    cudaGetSymbolAddress((void**)&xn2,  g_xn2);
    cudaGetSymbolAddress((void**)&hbuf, g_h);
    cudaGetSymbolAddress((void**)&wall, g_wall);
    cudaGetSymbolAddress((void**)&bpre, g_bias);

    __half* wq = wall + WOFF_QKV;
    __half* wp = wall + WOFF_PROJ;
    __half* w1 = wall + WOFF_FC1;
    __half* w2 = wall + WOFF_FC2;

    cudaFuncSetAttribute(gemm_kernel<768, 256, 0>,  cudaFuncAttributeMaxDynamicSharedMemorySize, GSMEM);
    cudaFuncSetAttribute(gemm_kernel<256, 256, 1>,  cudaFuncAttributeMaxDynamicSharedMemorySize, GSMEM);
    cudaFuncSetAttribute(gemm_kernel<1024, 256, 2>, cudaFuncAttributeMaxDynamicSharedMemorySize, GSMEM);
    cudaFuncSetAttribute(gemm_kernel<256, 1024, 3>, cudaFuncAttributeMaxDynamicSharedMemorySize, GSMEM);
    cudaFuncSetAttribute(attn_kernel, cudaFuncAttributeMaxDynamicSharedMemorySize, ATT_SMEM);

    cvt_all_kernel<<<WTOT / 8 / 256, 256>>>(w_qkv, w_proj, w_fc1, w_fc2, wall);
    bias_kernel<<<HEADS * 64 * 64 / 256, 256>>>(btab, bpre);
    ln_kernel<1><<<TTOK / 8, 256>>>(x, g1, b1, xw);
    gemm_kernel<768, 256, 0><<<dim3(TTOK / 128, 6), 256, GSMEM>>>(
        xw, wq, b_qkv, nullptr, nullptr, qkv);
    attn_kernel<<<2048, 256, ATT_SMEM>>>(qkv, bpre, attn);
    gemm_kernel<256, 256, 1><<<dim3(TTOK / 128, 2), 256, GSMEM>>>(
        attn, wp, b_proj, x, x1, nullptr);
    ln_kernel<0><<<TTOK / 8, 256>>>(x1, g2, b2, xn2);
    gemm_kernel<1024, 256, 2><<<dim3(TTOK / 128, 8), 256, GSMEM>>>(
        xn2, w1, b_fc1, nullptr, nullptr, hbuf);
    gemm_kernel<256, 1024, 3><<<dim3(TTOK / 128, 2), 256, GSMEM>>>(
        hbuf, w2, b_fc2, x1, out, nullptr);
}